// round 5
// baseline (speedup 1.0000x reference)
#include <cuda_runtime.h>
#include <cuda_fp16.h>
#include <cstdint>

#define TT   2048
#define HQn  16
#define HKVn 4
#define DH   128
#define BM   128
#define BN   64
#define NTH  256

// ---------------- smem layout (bytes) ----------------
#define OFF_Q    0
#define OFF_K(s) (32768 + (s) * 32768)
#define OFF_V(s) (OFF_K(s) + 16384)
#define OFF_P    98304
#define OFF_LB   OFF_P            // reused after mainloop
#define SMEM_TOTAL 114688

// ---------------- global fp16 scratch ----------------
__device__ __align__(16) __half g_qh[(size_t)TT * HQn * DH];
__device__ __align__(16) __half g_kh[(size_t)TT * HKVn * DH];
__device__ __align__(16) __half g_vh[(size_t)TT * HKVn * DH];

// ---------------- helpers ----------------
__device__ __forceinline__ uint32_t smem_u32(const void* p) {
    uint32_t a;
    asm("{ .reg .u64 t; cvta.to.shared.u64 t, %1; cvt.u32.u64 %0, t; }" : "=r"(a) : "l"(p));
    return a;
}
__device__ __forceinline__ int swz(int c, int row) {      // 16B-chunk swizzle
    return (c & 8) | ((c ^ row) & 7);
}
__device__ __forceinline__ void cpa(uint32_t dst, const void* src) {
    asm volatile("cp.async.cg.shared.global [%0], [%1], 16;" :: "r"(dst), "l"(src));
}
#define CP_COMMIT() asm volatile("cp.async.commit_group;" ::: "memory")
#define CP_WAIT0()  asm volatile("cp.async.wait_group 0;" ::: "memory")

__device__ __forceinline__ void ldsm4(uint32_t* r, uint32_t a) {
    asm volatile("ldmatrix.sync.aligned.m8n8.x4.shared.b16 {%0,%1,%2,%3}, [%4];"
                 : "=r"(r[0]), "=r"(r[1]), "=r"(r[2]), "=r"(r[3]) : "r"(a));
}
__device__ __forceinline__ void ldsm4t(uint32_t* r, uint32_t a) {
    asm volatile("ldmatrix.sync.aligned.m8n8.x4.trans.shared.b16 {%0,%1,%2,%3}, [%4];"
                 : "=r"(r[0]), "=r"(r[1]), "=r"(r[2]), "=r"(r[3]) : "r"(a));
}
__device__ __forceinline__ void hmma(float* d, const uint32_t* a, const uint32_t* b) {
    asm volatile("mma.sync.aligned.m16n8k16.row.col.f32.f16.f16.f32 "
                 "{%0,%1,%2,%3}, {%4,%5,%6,%7}, {%8,%9}, {%0,%1,%2,%3};"
                 : "+f"(d[0]), "+f"(d[1]), "+f"(d[2]), "+f"(d[3])
                 : "r"(a[0]), "r"(a[1]), "r"(a[2]), "r"(a[3]), "r"(b[0]), "r"(b[1]));
}
__device__ __forceinline__ float ex2(float x) {
    float r;
    asm("ex2.approx.ftz.f32 %0, %1;" : "=f"(r) : "f"(x));
    return r;
}

// ---------------- prepasses ----------------
__global__ void ropeq(const float* __restrict__ q, const float* __restrict__ cs,
                      const float* __restrict__ sn) {
    int lin = blockIdx.x * 256 + threadIdx.x;
    int row = lin >> 6;            // 64 threads per (t,h) row
    int j   = lin & 63;
    int tq  = row >> 4;
    size_t base = (size_t)row * DH;
    float2 xv = *(const float2*)(q + base + 2 * j);
    float2 xo = *(const float2*)(q + base + ((2 * j) ^ 64));
    int ci = (2 * j) & 63;
    float c0 = cs[tq * 64 + ci],     s0 = sn[tq * 64 + ci];
    float c1 = cs[tq * 64 + ci + 1], s1 = sn[tq * 64 + ci + 1];
    float sg = (j < 32) ? -1.f : 1.f;
    float r0 = xv.x * c0 + sg * xo.x * s0;
    float r1 = xv.y * c1 + sg * xo.y * s1;
    *(__half2*)(g_qh + base + 2 * j) = __floats2half2_rn(r0, r1);
}
__global__ void ropek(const float* __restrict__ k, const float* __restrict__ cs,
                      const float* __restrict__ sn) {
    int lin = blockIdx.x * 256 + threadIdx.x;
    int row = lin >> 6;
    int j   = lin & 63;
    int tk  = row >> 2;
    size_t base = (size_t)row * DH;
    float2 xv = *(const float2*)(k + base + 2 * j);
    float2 xo = *(const float2*)(k + base + ((2 * j) ^ 64));
    int ci = (2 * j) & 63;
    float c0 = cs[tk * 64 + ci],     s0 = sn[tk * 64 + ci];
    float c1 = cs[tk * 64 + ci + 1], s1 = sn[tk * 64 + ci + 1];
    float sg = (j < 32) ? -1.f : 1.f;
    float r0 = xv.x * c0 + sg * xo.x * s0;
    float r1 = xv.y * c1 + sg * xo.y * s1;
    *(__half2*)(g_kh + base + 2 * j) = __floats2half2_rn(r0, r1);
}
__global__ void vconv(const float* __restrict__ v) {
    size_t i = ((size_t)blockIdx.x * 256 + threadIdx.x) * 4;
    float4 f = *(const float4*)(v + i);
    ((__half2*)(g_vh + i))[0] = __floats2half2_rn(f.x, f.y);
    ((__half2*)(g_vh + i))[1] = __floats2half2_rn(f.z, f.w);
}

// ---------------- K/V tile loader (cp.async) ----------------
__device__ __forceinline__ void load_tile(uint32_t sb, int t0, int stage, int hk, int tid) {
    const uint32_t Kb = sb + OFF_K(stage), Vb = sb + OFF_V(stage);
#pragma unroll
    for (int j = 0; j < 4; ++j) {
        int idx = tid + j * 256;
        int row = idx >> 4, c = idx & 15;
        size_t g = ((size_t)(t0 + row) * HKVn + hk) * DH + c * 8;
        uint32_t so = row * 256 + swz(c, row) * 16;
        cpa(Kb + so, g_kh + g);
        cpa(Vb + so, g_vh + g);
    }
}

// ---------------- main attention kernel ----------------
__global__ __launch_bounds__(NTH, 2)
void attn_kernel(const int* __restrict__ qranges,
                 const int* __restrict__ kranges,
                 int nR, float* __restrict__ out) {
    extern __shared__ char smem[];
    const uint32_t sb = smem_u32(smem);
    const int tid  = threadIdx.x;
    const int wid  = tid >> 5;
    const int lane = tid & 31;
    const int g    = lane >> 2;
    const int tq4  = lane & 3;

    const int head = blockIdx.x & 15;
    const int qt   = 15 - (blockIdx.x >> 4);   // heavy-first
    const int q0   = qt * BM;
    const int hk   = head >> 2;

    const int mwBase = (wid & 3) * 32;   // q rows this warp owns (2 m-frags)
    const int nw     = wid >> 2;         // QK: key group (nw*32); PV: d group (nw*64)

    int kEnd = 0;
    for (int r = 0; r < nR; ++r) {
        int qs = qranges[2 * r], qe = qranges[2 * r + 1];
        if (q0 >= qs && q0 < qe) { int ke = kranges[2 * r + 1]; if (ke > kEnd) kEnd = ke; }
    }
    const int nt = kEnd / BN;

    // ---- prologue: Q + tile 0, one cp.async group ----
#pragma unroll
    for (int j = 0; j < 8; ++j) {
        int idx = tid + j * 256;
        int row = idx >> 4, c = idx & 15;
        size_t gof = ((size_t)(q0 + row) * HQn + head) * DH + c * 8;
        cpa(sb + OFF_Q + row * 256 + swz(c, row) * 16, g_qh + gof);
    }
    load_tile(sb, 0, 0, hk, tid);
    CP_COMMIT();

    float O[2][8][4];
    float lsum[2][2];
#pragma unroll
    for (int mf = 0; mf < 2; ++mf) {
        lsum[mf][0] = lsum[mf][1] = 0.f;
#pragma unroll
        for (int nf = 0; nf < 8; ++nf)
#pragma unroll
            for (int e = 0; e < 4; ++e) O[mf][nf][e] = 0.f;
    }

    const float kC = 0.127532019f;   // log2(e)/sqrt(128)

    for (int t = 0; t < nt; ++t) {
        const int s = t & 1;

        CP_WAIT0();
        __syncthreads();                       // tile t ready; PV(t-1) done everywhere
        if (t + 1 < nt) { load_tile(sb, (t + 1) * BN, s ^ 1, hk, tid); CP_COMMIT(); }

        // ---------- QK: S(m32 x n32) = Q . K^T ----------
        float S[2][4][4];
#pragma unroll
        for (int mf = 0; mf < 2; ++mf)
#pragma unroll
            for (int nf = 0; nf < 4; ++nf)
#pragma unroll
                for (int e = 0; e < 4; ++e) S[mf][nf][e] = 0.f;

        const uint32_t Kb = sb + OFF_K(s);
        const uint32_t Qb = sb + OFF_Q;
#pragma unroll
        for (int ks = 0; ks < 8; ++ks) {
            uint32_t kb[8];
            {
                int rowK = nw * 32 + ((lane >> 4) << 3) + (lane & 7);
                int ch = 2 * ks + ((lane >> 3) & 1);
                ldsm4(kb,     Kb + rowK * 256 + swz(ch, rowK) * 16);
                int rowK2 = rowK + 16;
                ldsm4(kb + 4, Kb + rowK2 * 256 + swz(ch, rowK2) * 16);
            }
#pragma unroll
            for (int mf = 0; mf < 2; ++mf) {
                uint32_t a[4];
                int rowA = mwBase + mf * 16 + (lane & 15);
                int ch = 2 * ks + (lane >> 4);
                ldsm4(a, Qb + rowA * 256 + swz(ch, rowA) * 16);
                hmma(S[mf][0], a, kb + 0);
                hmma(S[mf][1], a, kb + 2);
                hmma(S[mf][2], a, kb + 4);
                hmma(S[mf][3], a, kb + 6);
            }
        }

        // ---------- softmax (no max-sub) + P to smem ----------
        {
            char* PH = smem + OFF_P;
#pragma unroll
            for (int mf = 0; mf < 2; ++mf) {
                int rg = mwBase + mf * 16 + g;
                int rh = rg + 8;
#pragma unroll
                for (int nf = 0; nf < 4; ++nf) {
                    float p0 = ex2(S[mf][nf][0] * kC);
                    float p1 = ex2(S[mf][nf][1] * kC);
                    float p2 = ex2(S[mf][nf][2] * kC);
                    float p3 = ex2(S[mf][nf][3] * kC);
                    lsum[mf][0] += p0 + p1;
                    lsum[mf][1] += p2 + p3;
                    int c = nw * 4 + nf;
                    int b0 = rg * 128 + ((c ^ (rg & 7)) * 16) + 4 * tq4;
                    int b1 = rh * 128 + ((c ^ (rh & 7)) * 16) + 4 * tq4;
                    *(__half2*)(PH + b0) = __floats2half2_rn(p0, p1);
                    *(__half2*)(PH + b1) = __floats2half2_rn(p2, p3);
                }
            }
        }
        __syncthreads();                       // P visible; K(s) reads done

        // ---------- PV: O(m32 x d64) += P . V ----------
        const uint32_t Vb = sb + OFF_V(s);
        const uint32_t Pa = sb + OFF_P;
#pragma unroll
        for (int ks = 0; ks < 4; ++ks) {
            uint32_t vb[16];
#pragma unroll
            for (int nfp = 0; nfp < 4; ++nfp) {
                int rowV = ks * 16 + (lane & 15);
                int cd = nw * 8 + nfp * 2 + (lane >> 4);
                ldsm4t(vb + nfp * 4, Vb + rowV * 256 + swz(cd, rowV) * 16);
            }
#pragma unroll
            for (int mf = 0; mf < 2; ++mf) {
                uint32_t a[4];
                int rowA = mwBase + mf * 16 + (lane & 15);
                int ch = 2 * ks + (lane >> 4);
                ldsm4(a, Pa + rowA * 128 + ((ch ^ (rowA & 7)) * 16));
#pragma unroll
                for (int nf = 0; nf < 8; ++nf)
                    hmma(O[mf][nf], a, vb + nf * 2);
            }
        }
    }

    // ---- l reduction across quad lanes; lb reuses P space ----
    __syncthreads();                           // last PV reads of P done
    float* lb = (float*)(smem + OFF_LB);
#pragma unroll
    for (int mf = 0; mf < 2; ++mf)
#pragma unroll
        for (int h = 0; h < 2; ++h) {
            float v = lsum[mf][h];
            v += __shfl_xor_sync(0xffffffffu, v, 1);
            v += __shfl_xor_sync(0xffffffffu, v, 2);
            lsum[mf][h] = v;
        }
    if (tq4 == 0) {
#pragma unroll
        for (int mf = 0; mf < 2; ++mf) {
            int rg = mwBase + mf * 16 + g;
            lb[rg * 2 + nw]       = lsum[mf][0];
            lb[(rg + 8) * 2 + nw] = lsum[mf][1];
        }
    }
    __syncthreads();

    // ---- epilogue: normalize + store ----
#pragma unroll
    for (int mf = 0; mf < 2; ++mf) {
        int rg = mwBase + mf * 16 + g;
        int rh = rg + 8;
        float ig = 1.0f / (lb[rg * 2] + lb[rg * 2 + 1]);
        float ih = 1.0f / (lb[rh * 2] + lb[rh * 2 + 1]);
        float* og = out + ((size_t)(q0 + rg) * HQn + head) * DH;
        float* oh = out + ((size_t)(q0 + rh) * HQn + head) * DH;
#pragma unroll
        for (int nf = 0; nf < 8; ++nf) {
            int d = nw * 64 + nf * 8 + 2 * tq4;
            *(float2*)(og + d) = make_float2(O[mf][nf][0] * ig, O[mf][nf][1] * ig);
            *(float2*)(oh + d) = make_float2(O[mf][nf][2] * ih, O[mf][nf][3] * ih);
        }
    }
}

extern "C" void kernel_launch(void* const* d_in, const int* in_sizes, int n_in,
                              void* d_out, int out_size) {
    const float* q  = (const float*)d_in[0];
    const float* k  = (const float*)d_in[1];
    const float* v  = (const float*)d_in[2];
    const float* cs = (const float*)d_in[3];
    const float* sn = (const float*)d_in[4];
    const int*   qr = (const int*)d_in[5];
    const int*   kr = (const int*)d_in[6];
    const int nR = in_sizes[5] / 2;
    float* out = (float*)d_out;

    cudaFuncSetAttribute(attn_kernel,
                         cudaFuncAttributeMaxDynamicSharedMemorySize, SMEM_TOTAL);

    ropeq<<<(TT * HQn * 64) / 256, 256>>>(q, cs, sn);
    ropek<<<(TT * HKVn * 64) / 256, 256>>>(k, cs, sn);
    vconv<<<(TT * HKVn * DH) / 1024, 256>>>(v);
    attn_kernel<<<(TT / BM) * HQn, NTH, SMEM_TOTAL>>>(qr, kr, nR, out);
}

// round 6
// speedup vs baseline: 1.0690x; 1.0690x over previous
#include <cuda_runtime.h>
#include <cuda_fp16.h>
#include <cstdint>

#define TT   2048
#define HQn  16
#define HKVn 4
#define DH   128
#define BM   128
#define BN   64
#define NTH  256
#define CHUNK_TILES 8           // key-tiles per split-K chunk (512 keys)
#define MAXCH 4                 // max chunks per (head, q-tile)

// ---------------- smem layout (bytes) ----------------
#define OFF_Q    0
#define OFF_K(s) (32768 + (s) * 32768)
#define OFF_V(s) (OFF_K(s) + 16384)
#define OFF_P    98304
#define OFF_LB   OFF_P            // reused after mainloop
#define SMEM_TOTAL 114688

// ---------------- global scratch ----------------
__device__ __align__(16) __half g_qh[(size_t)TT * HQn * DH];
__device__ __align__(16) __half g_kh[(size_t)TT * HKVn * DH];
__device__ __align__(16) __half g_vh[(size_t)TT * HKVn * DH];
// split-K partials: slot = ((head*16 + qt)*MAXCH + chunk)
__device__ __align__(16) float g_po[(size_t)HQn * 16 * MAXCH * BM * DH];
__device__ float g_pl[(size_t)HQn * 16 * MAXCH * BM];

// ---------------- helpers ----------------
__device__ __forceinline__ uint32_t smem_u32(const void* p) {
    uint32_t a;
    asm("{ .reg .u64 t; cvta.to.shared.u64 t, %1; cvt.u32.u64 %0, t; }" : "=r"(a) : "l"(p));
    return a;
}
__device__ __forceinline__ int swz(int c, int row) {      // 16B-chunk swizzle
    return (c & 8) | ((c ^ row) & 7);
}
__device__ __forceinline__ void cpa(uint32_t dst, const void* src) {
    asm volatile("cp.async.cg.shared.global [%0], [%1], 16;" :: "r"(dst), "l"(src));
}
#define CP_COMMIT() asm volatile("cp.async.commit_group;" ::: "memory")
#define CP_WAIT0()  asm volatile("cp.async.wait_group 0;" ::: "memory")

__device__ __forceinline__ void ldsm4(uint32_t* r, uint32_t a) {
    asm volatile("ldmatrix.sync.aligned.m8n8.x4.shared.b16 {%0,%1,%2,%3}, [%4];"
                 : "=r"(r[0]), "=r"(r[1]), "=r"(r[2]), "=r"(r[3]) : "r"(a));
}
__device__ __forceinline__ void ldsm4t(uint32_t* r, uint32_t a) {
    asm volatile("ldmatrix.sync.aligned.m8n8.x4.trans.shared.b16 {%0,%1,%2,%3}, [%4];"
                 : "=r"(r[0]), "=r"(r[1]), "=r"(r[2]), "=r"(r[3]) : "r"(a));
}
__device__ __forceinline__ void hmma(float* d, const uint32_t* a, const uint32_t* b) {
    asm volatile("mma.sync.aligned.m16n8k16.row.col.f32.f16.f16.f32 "
                 "{%0,%1,%2,%3}, {%4,%5,%6,%7}, {%8,%9}, {%0,%1,%2,%3};"
                 : "+f"(d[0]), "+f"(d[1]), "+f"(d[2]), "+f"(d[3])
                 : "r"(a[0]), "r"(a[1]), "r"(a[2]), "r"(a[3]), "r"(b[0]), "r"(b[1]));
}
__device__ __forceinline__ float ex2(float x) {
    float r;
    asm("ex2.approx.ftz.f32 %0, %1;" : "=f"(r) : "f"(x));
    return r;
}

// ---------------- prepasses ----------------
__global__ void ropeq(const float* __restrict__ q, const float* __restrict__ cs,
                      const float* __restrict__ sn) {
    int lin = blockIdx.x * 256 + threadIdx.x;
    int row = lin >> 6;            // 64 threads per (t,h) row
    int j   = lin & 63;
    int tq  = row >> 4;
    size_t base = (size_t)row * DH;
    float2 xv = *(const float2*)(q + base + 2 * j);
    float2 xo = *(const float2*)(q + base + ((2 * j) ^ 64));
    int ci = (2 * j) & 63;
    float c0 = cs[tq * 64 + ci],     s0 = sn[tq * 64 + ci];
    float c1 = cs[tq * 64 + ci + 1], s1 = sn[tq * 64 + ci + 1];
    float sg = (j < 32) ? -1.f : 1.f;
    float r0 = xv.x * c0 + sg * xo.x * s0;
    float r1 = xv.y * c1 + sg * xo.y * s1;
    *(__half2*)(g_qh + base + 2 * j) = __floats2half2_rn(r0, r1);
}
__global__ void ropek(const float* __restrict__ k, const float* __restrict__ cs,
                      const float* __restrict__ sn) {
    int lin = blockIdx.x * 256 + threadIdx.x;
    int row = lin >> 6;
    int j   = lin & 63;
    int tk  = row >> 2;
    size_t base = (size_t)row * DH;
    float2 xv = *(const float2*)(k + base + 2 * j);
    float2 xo = *(const float2*)(k + base + ((2 * j) ^ 64));
    int ci = (2 * j) & 63;
    float c0 = cs[tk * 64 + ci],     s0 = sn[tk * 64 + ci];
    float c1 = cs[tk * 64 + ci + 1], s1 = sn[tk * 64 + ci + 1];
    float sg = (j < 32) ? -1.f : 1.f;
    float r0 = xv.x * c0 + sg * xo.x * s0;
    float r1 = xv.y * c1 + sg * xo.y * s1;
    *(__half2*)(g_kh + base + 2 * j) = __floats2half2_rn(r0, r1);
}
__global__ void vconv(const float* __restrict__ v) {
    size_t i = ((size_t)blockIdx.x * 256 + threadIdx.x) * 4;
    float4 f = *(const float4*)(v + i);
    ((__half2*)(g_vh + i))[0] = __floats2half2_rn(f.x, f.y);
    ((__half2*)(g_vh + i))[1] = __floats2half2_rn(f.z, f.w);
}

// ---------------- K/V tile loader (cp.async) ----------------
__device__ __forceinline__ void load_tile(uint32_t sb, int t0, int stage, int hk, int tid) {
    const uint32_t Kb = sb + OFF_K(stage), Vb = sb + OFF_V(stage);
#pragma unroll
    for (int j = 0; j < 4; ++j) {
        int idx = tid + j * 256;
        int row = idx >> 4, c = idx & 15;
        size_t g = ((size_t)(t0 + row) * HKVn + hk) * DH + c * 8;
        uint32_t so = row * 256 + swz(c, row) * 16;
        cpa(Kb + so, g_kh + g);
        cpa(Vb + so, g_vh + g);
    }
}

__device__ __forceinline__ int kend_for(const int* qranges, const int* kranges,
                                        int nR, int q0) {
    int kEnd = 0;
    for (int r = 0; r < nR; ++r) {
        int qs = qranges[2 * r], qe = qranges[2 * r + 1];
        if (q0 >= qs && q0 < qe) { int ke = kranges[2 * r + 1]; if (ke > kEnd) kEnd = ke; }
    }
    return kEnd;
}

// ---------------- main attention kernel (split-K) ----------------
__global__ __launch_bounds__(NTH, 2)
void attn_kernel(const int* __restrict__ qranges,
                 const int* __restrict__ kranges,
                 int nR, float* __restrict__ out) {
    extern __shared__ char smem[];
    const uint32_t sb = smem_u32(smem);
    const int tid  = threadIdx.x;
    const int wid  = tid >> 5;
    const int lane = tid & 31;
    const int g    = lane >> 2;
    const int tq4  = lane & 3;

    const int head  = blockIdx.x & 15;
    const int chunk = (blockIdx.x >> 4) & 3;
    const int qt    = 15 - (blockIdx.x >> 6);   // heavy-first
    const int q0    = qt * BM;
    const int hk    = head >> 2;

    const int kEnd = kend_for(qranges, kranges, nR, q0);
    const int nt   = kEnd / BN;
    const int nch  = (nt + CHUNK_TILES - 1) / CHUNK_TILES;
    if (chunk >= nch) return;
    const int tS = chunk * CHUNK_TILES;
    const int tE = min(nt, tS + CHUNK_TILES);

    const int mwBase = (wid & 3) * 32;   // q rows this warp owns (2 m-frags)
    const int nw     = wid >> 2;         // QK: key group; PV: d group

    // ---- prologue: Q + first tile, one cp.async group ----
#pragma unroll
    for (int j = 0; j < 8; ++j) {
        int idx = tid + j * 256;
        int row = idx >> 4, c = idx & 15;
        size_t gof = ((size_t)(q0 + row) * HQn + head) * DH + c * 8;
        cpa(sb + OFF_Q + row * 256 + swz(c, row) * 16, g_qh + gof);
    }
    load_tile(sb, tS * BN, 0, hk, tid);
    CP_COMMIT();

    float O[2][8][4];
    float lsum[2][2];
#pragma unroll
    for (int mf = 0; mf < 2; ++mf) {
        lsum[mf][0] = lsum[mf][1] = 0.f;
#pragma unroll
        for (int nf = 0; nf < 8; ++nf)
#pragma unroll
            for (int e = 0; e < 4; ++e) O[mf][nf][e] = 0.f;
    }

    const float kC = 0.127532019f;   // log2(e)/sqrt(128)

    for (int t = tS; t < tE; ++t) {
        const int s = (t - tS) & 1;

        CP_WAIT0();
        __syncthreads();                       // tile t ready; PV(t-1) done everywhere
        if (t + 1 < tE) { load_tile(sb, (t + 1) * BN, s ^ 1, hk, tid); CP_COMMIT(); }

        // ---------- QK: S(m32 x n32) = Q . K^T ----------
        float S[2][4][4];
#pragma unroll
        for (int mf = 0; mf < 2; ++mf)
#pragma unroll
            for (int nf = 0; nf < 4; ++nf)
#pragma unroll
                for (int e = 0; e < 4; ++e) S[mf][nf][e] = 0.f;

        const uint32_t Kb = sb + OFF_K(s);
        const uint32_t Qb = sb + OFF_Q;
#pragma unroll
        for (int ks = 0; ks < 8; ++ks) {
            uint32_t kb[8];
            {
                int rowK = nw * 32 + ((lane >> 4) << 3) + (lane & 7);
                int ch = 2 * ks + ((lane >> 3) & 1);
                ldsm4(kb,     Kb + rowK * 256 + swz(ch, rowK) * 16);
                int rowK2 = rowK + 16;
                ldsm4(kb + 4, Kb + rowK2 * 256 + swz(ch, rowK2) * 16);
            }
#pragma unroll
            for (int mf = 0; mf < 2; ++mf) {
                uint32_t a[4];
                int rowA = mwBase + mf * 16 + (lane & 15);
                int ch = 2 * ks + (lane >> 4);
                ldsm4(a, Qb + rowA * 256 + swz(ch, rowA) * 16);
                hmma(S[mf][0], a, kb + 0);
                hmma(S[mf][1], a, kb + 2);
                hmma(S[mf][2], a, kb + 4);
                hmma(S[mf][3], a, kb + 6);
            }
        }

        // ---------- softmax (no max-sub) + P to smem ----------
        {
            char* PH = smem + OFF_P;
#pragma unroll
            for (int mf = 0; mf < 2; ++mf) {
                int rg = mwBase + mf * 16 + g;
                int rh = rg + 8;
#pragma unroll
                for (int nf = 0; nf < 4; ++nf) {
                    float p0 = ex2(S[mf][nf][0] * kC);
                    float p1 = ex2(S[mf][nf][1] * kC);
                    float p2 = ex2(S[mf][nf][2] * kC);
                    float p3 = ex2(S[mf][nf][3] * kC);
                    lsum[mf][0] += p0 + p1;
                    lsum[mf][1] += p2 + p3;
                    int c = nw * 4 + nf;
                    int b0 = rg * 128 + ((c ^ (rg & 7)) * 16) + 4 * tq4;
                    int b1 = rh * 128 + ((c ^ (rh & 7)) * 16) + 4 * tq4;
                    *(__half2*)(PH + b0) = __floats2half2_rn(p0, p1);
                    *(__half2*)(PH + b1) = __floats2half2_rn(p2, p3);
                }
            }
        }
        __syncthreads();                       // P visible; K(s) reads done

        // ---------- PV: O(m32 x d64) += P . V ----------
        const uint32_t Vb = sb + OFF_V(s);
        const uint32_t Pa = sb + OFF_P;
#pragma unroll
        for (int ks = 0; ks < 4; ++ks) {
            uint32_t vb[16];
#pragma unroll
            for (int nfp = 0; nfp < 4; ++nfp) {
                int rowV = ks * 16 + (lane & 15);
                int cd = nw * 8 + nfp * 2 + (lane >> 4);
                ldsm4t(vb + nfp * 4, Vb + rowV * 256 + swz(cd, rowV) * 16);
            }
#pragma unroll
            for (int mf = 0; mf < 2; ++mf) {
                uint32_t a[4];
                int rowA = mwBase + mf * 16 + (lane & 15);
                int ch = 2 * ks + (lane >> 4);
                ldsm4(a, Pa + rowA * 128 + ((ch ^ (rowA & 7)) * 16));
#pragma unroll
                for (int nf = 0; nf < 8; ++nf)
                    hmma(O[mf][nf], a, vb + nf * 2);
            }
        }
    }

    // ---- l reduction across quad lanes; lb reuses P space ----
    __syncthreads();                           // last PV reads of P done
    float* lb = (float*)(smem + OFF_LB);
#pragma unroll
    for (int mf = 0; mf < 2; ++mf)
#pragma unroll
        for (int h = 0; h < 2; ++h) {
            float v = lsum[mf][h];
            v += __shfl_xor_sync(0xffffffffu, v, 1);
            v += __shfl_xor_sync(0xffffffffu, v, 2);
            lsum[mf][h] = v;
        }
    if (tq4 == 0) {
#pragma unroll
        for (int mf = 0; mf < 2; ++mf) {
            int rg = mwBase + mf * 16 + g;
            lb[rg * 2 + nw]       = lsum[mf][0];
            lb[(rg + 8) * 2 + nw] = lsum[mf][1];
        }
    }
    __syncthreads();

    if (nch == 1) {
        // ---- direct epilogue: normalize + store ----
#pragma unroll
        for (int mf = 0; mf < 2; ++mf) {
            int rg = mwBase + mf * 16 + g;
            int rh = rg + 8;
            float ig = 1.0f / (lb[rg * 2] + lb[rg * 2 + 1]);
            float ih = 1.0f / (lb[rh * 2] + lb[rh * 2 + 1]);
            float* og = out + ((size_t)(q0 + rg) * HQn + head) * DH;
            float* oh = out + ((size_t)(q0 + rh) * HQn + head) * DH;
#pragma unroll
            for (int nf = 0; nf < 8; ++nf) {
                int d = nw * 64 + nf * 8 + 2 * tq4;
                *(float2*)(og + d) = make_float2(O[mf][nf][0] * ig, O[mf][nf][1] * ig);
                *(float2*)(oh + d) = make_float2(O[mf][nf][2] * ih, O[mf][nf][3] * ih);
            }
        }
    } else {
        // ---- split epilogue: unnormalized partial O + l to scratch ----
        const size_t slot = ((size_t)(head * 16 + qt) * MAXCH + chunk);
        float* po = g_po + slot * (BM * DH);
        float* pl = g_pl + slot * BM;
#pragma unroll
        for (int mf = 0; mf < 2; ++mf) {
            int rg = mwBase + mf * 16 + g;
            int rh = rg + 8;
            if (tq4 == 0 && nw == 0) {
                pl[rg] = lb[rg * 2] + lb[rg * 2 + 1];
                pl[rh] = lb[rh * 2] + lb[rh * 2 + 1];
            }
            float* og = po + rg * DH;
            float* oh = po + rh * DH;
#pragma unroll
            for (int nf = 0; nf < 8; ++nf) {
                int d = nw * 64 + nf * 8 + 2 * tq4;
                *(float2*)(og + d) = make_float2(O[mf][nf][0], O[mf][nf][1]);
                *(float2*)(oh + d) = make_float2(O[mf][nf][2], O[mf][nf][3]);
            }
        }
    }
}

// ---------------- split-K reduction ----------------
__global__ __launch_bounds__(256, 4)
void reduce_kernel(const int* __restrict__ qranges,
                   const int* __restrict__ kranges,
                   int nR, float* __restrict__ out) {
    const int head = blockIdx.x & 15;
    const int qt   = blockIdx.x >> 4;
    const int q0   = qt * BM;
    const int kEnd = kend_for(qranges, kranges, nR, q0);
    const int nt   = kEnd / BN;
    const int nch  = (nt + CHUNK_TILES - 1) / CHUNK_TILES;
    if (nch <= 1) return;

    __shared__ float linv[BM];
    const int tid = threadIdx.x;
    const size_t base = (size_t)(head * 16 + qt) * MAXCH;

    if (tid < BM) {
        float l = 0.f;
        for (int c = 0; c < nch; ++c) l += g_pl[(base + c) * BM + tid];
        linv[tid] = 1.0f / l;
    }
    __syncthreads();

    const float4* po = (const float4*)(g_po + base * (BM * DH));
#pragma unroll
    for (int i = 0; i < 16; ++i) {
        int idx = tid + i * 256;               // 4096 float4 = 128x128
        int row = idx >> 5;
        float4 acc = po[idx];
        for (int c = 1; c < nch; ++c) {
            float4 v = po[(size_t)c * (BM * DH / 4) + idx];
            acc.x += v.x; acc.y += v.y; acc.z += v.z; acc.w += v.w;
        }
        float s = linv[row];
        acc.x *= s; acc.y *= s; acc.z *= s; acc.w *= s;
        int d = (idx & 31) * 4;
        *(float4*)(out + ((size_t)(q0 + row) * HQn + head) * DH + d) = acc;
    }
}

extern "C" void kernel_launch(void* const* d_in, const int* in_sizes, int n_in,
                              void* d_out, int out_size) {
    const float* q  = (const float*)d_in[0];
    const float* k  = (const float*)d_in[1];
    const float* v  = (const float*)d_in[2];
    const float* cs = (const float*)d_in[3];
    const float* sn = (const float*)d_in[4];
    const int*   qr = (const int*)d_in[5];
    const int*   kr = (const int*)d_in[6];
    const int nR = in_sizes[5] / 2;
    float* out = (float*)d_out;

    cudaFuncSetAttribute(attn_kernel,
                         cudaFuncAttributeMaxDynamicSharedMemorySize, SMEM_TOTAL);

    ropeq<<<(TT * HQn * 64) / 256, 256>>>(q, cs, sn);
    ropek<<<(TT * HKVn * 64) / 256, 256>>>(k, cs, sn);
    vconv<<<(TT * HKVn * DH) / 1024, 256>>>(v);
    attn_kernel<<<(TT / BM) * HQn * MAXCH, NTH, SMEM_TOTAL>>>(qr, kr, nR, out);
    reduce_kernel<<<(TT / BM) * HQn, 256>>>(qr, kr, nR, out);
}

// round 8
// speedup vs baseline: 1.1402x; 1.0666x over previous
#include <cuda_runtime.h>
#include <cuda_fp16.h>
#include <cstdint>

#define TT   2048
#define HQn  16
#define HKVn 4
#define DH   128
#define BM   128
#define BN   64
#define NTH  256
#define CHUNK_TILES 8           // max key-tiles per split-K chunk
#define MAXCH 4                 // max chunks per (head, q-tile)

// ---------------- smem layout (bytes) ----------------
#define OFF_Q    0
#define OFF_K(s) (32768 + (s) * 32768)
#define OFF_V(s) (OFF_K(s) + 16384)
#define OFF_P    98304
#define OFF_LB   OFF_P            // reused after mainloop (1KB)
#define OFF_FLAG (OFF_P + 2048)   // int flag for reducer election
#define SMEM_TOTAL 114688

// ---------------- global scratch ----------------
__device__ __align__(16) __half g_qh[(size_t)TT * HQn * DH];
__device__ __align__(16) __half g_kh[(size_t)TT * HKVn * DH];
__device__ __align__(16) __half g_vh[(size_t)TT * HKVn * DH];
// split-K partials: slot = ((head*16 + qt)*MAXCH + chunk)
__device__ __align__(16) float g_po[(size_t)HQn * 16 * MAXCH * BM * DH];
__device__ float g_pl[(size_t)HQn * 16 * MAXCH * BM];
__device__ int   g_cnt[HQn * 16];   // zero-init; reducer resets after use

// ---------------- helpers ----------------
__device__ __forceinline__ uint32_t smem_u32(const void* p) {
    uint32_t a;
    asm("{ .reg .u64 t; cvta.to.shared.u64 t, %1; cvt.u32.u64 %0, t; }" : "=r"(a) : "l"(p));
    return a;
}
__device__ __forceinline__ int swz(int c, int row) {      // 16B-chunk swizzle
    return (c & 8) | ((c ^ row) & 7);
}
__device__ __forceinline__ void cpa(uint32_t dst, const void* src) {
    asm volatile("cp.async.cg.shared.global [%0], [%1], 16;" :: "r"(dst), "l"(src));
}
#define CP_COMMIT() asm volatile("cp.async.commit_group;" ::: "memory")
#define CP_WAIT0()  asm volatile("cp.async.wait_group 0;" ::: "memory")

__device__ __forceinline__ void ldsm4(uint32_t* r, uint32_t a) {
    asm volatile("ldmatrix.sync.aligned.m8n8.x4.shared.b16 {%0,%1,%2,%3}, [%4];"
                 : "=r"(r[0]), "=r"(r[1]), "=r"(r[2]), "=r"(r[3]) : "r"(a));
}
__device__ __forceinline__ void ldsm4t(uint32_t* r, uint32_t a) {
    asm volatile("ldmatrix.sync.aligned.m8n8.x4.trans.shared.b16 {%0,%1,%2,%3}, [%4];"
                 : "=r"(r[0]), "=r"(r[1]), "=r"(r[2]), "=r"(r[3]) : "r"(a));
}
__device__ __forceinline__ void hmma(float* d, const uint32_t* a, const uint32_t* b) {
    asm volatile("mma.sync.aligned.m16n8k16.row.col.f32.f16.f16.f32 "
                 "{%0,%1,%2,%3}, {%4,%5,%6,%7}, {%8,%9}, {%0,%1,%2,%3};"
                 : "+f"(d[0]), "+f"(d[1]), "+f"(d[2]), "+f"(d[3])
                 : "r"(a[0]), "r"(a[1]), "r"(a[2]), "r"(a[3]), "r"(b[0]), "r"(b[1]));
}
__device__ __forceinline__ float ex2(float x) {
    float r;
    asm("ex2.approx.ftz.f32 %0, %1;" : "=f"(r) : "f"(x));
    return r;
}

// ---------------- fused prepass: rope(Q), rope(K), conv(V) ----------------
#define QBLK ((TT * HQn * 64) / 256)     // 8192
#define KBLK ((TT * HKVn * 64) / 256)    // 2048
#define VBLK ((TT * HKVn * DH) / 1024)   // 1024
__global__ void prep_kernel(const float* __restrict__ q, const float* __restrict__ k,
                            const float* __restrict__ v, const float* __restrict__ cs,
                            const float* __restrict__ sn) {
    int b = blockIdx.x;
    if (b < QBLK) {
        int lin = b * 256 + threadIdx.x;
        int row = lin >> 6, j = lin & 63;
        int tq = row >> 4;
        size_t base = (size_t)row * DH;
        float2 xv = *(const float2*)(q + base + 2 * j);
        float2 xo = *(const float2*)(q + base + ((2 * j) ^ 64));
        int ci = (2 * j) & 63;
        float c0 = cs[tq * 64 + ci],     s0 = sn[tq * 64 + ci];
        float c1 = cs[tq * 64 + ci + 1], s1 = sn[tq * 64 + ci + 1];
        float sg = (j < 32) ? -1.f : 1.f;
        *(__half2*)(g_qh + base + 2 * j) =
            __floats2half2_rn(xv.x * c0 + sg * xo.x * s0, xv.y * c1 + sg * xo.y * s1);
    } else if (b < QBLK + KBLK) {
        int lin = (b - QBLK) * 256 + threadIdx.x;
        int row = lin >> 6, j = lin & 63;
        int tk = row >> 2;
        size_t base = (size_t)row * DH;
        float2 xv = *(const float2*)(k + base + 2 * j);
        float2 xo = *(const float2*)(k + base + ((2 * j) ^ 64));
        int ci = (2 * j) & 63;
        float c0 = cs[tk * 64 + ci],     s0 = sn[tk * 64 + ci];
        float c1 = cs[tk * 64 + ci + 1], s1 = sn[tk * 64 + ci + 1];
        float sg = (j < 32) ? -1.f : 1.f;
        *(__half2*)(g_kh + base + 2 * j) =
            __floats2half2_rn(xv.x * c0 + sg * xo.x * s0, xv.y * c1 + sg * xo.y * s1);
    } else {
        size_t i = ((size_t)(b - QBLK - KBLK) * 256 + threadIdx.x) * 4;
        float4 f = *(const float4*)(v + i);
        ((__half2*)(g_vh + i))[0] = __floats2half2_rn(f.x, f.y);
        ((__half2*)(g_vh + i))[1] = __floats2half2_rn(f.z, f.w);
    }
}

// ---------------- K/V tile loader (cp.async) ----------------
__device__ __forceinline__ void load_tile(uint32_t sb, int t0, int stage, int hk, int tid) {
    const uint32_t Kb = sb + OFF_K(stage), Vb = sb + OFF_V(stage);
#pragma unroll
    for (int j = 0; j < 4; ++j) {
        int idx = tid + j * 256;
        int row = idx >> 4, c = idx & 15;
        size_t g = ((size_t)(t0 + row) * HKVn + hk) * DH + c * 8;
        uint32_t so = row * 256 + swz(c, row) * 16;
        cpa(Kb + so, g_kh + g);
        cpa(Vb + so, g_vh + g);
    }
}

// ---------------- main attention kernel (split-K, fused reduce) ----------------
__global__ __launch_bounds__(NTH, 2)
void attn_kernel(const int* __restrict__ qranges,
                 const int* __restrict__ kranges,
                 int nR, float* __restrict__ out) {
    extern __shared__ char smem[];
    const uint32_t sb = smem_u32(smem);
    const int tid  = threadIdx.x;
    const int wid  = tid >> 5;
    const int lane = tid & 31;
    const int g    = lane >> 2;
    const int tq4  = lane & 3;

    const int head  = blockIdx.x & 15;
    const int chunk = (blockIdx.x >> 4) & 3;
    const int qt    = 15 - (blockIdx.x >> 6);   // heavy-first
    const int q0    = qt * BM;
    const int hk    = head >> 2;

    int kEnd = 0;
    for (int r = 0; r < nR; ++r) {
        int qs = qranges[2 * r], qe = qranges[2 * r + 1];
        if (q0 >= qs && q0 < qe) { int ke = kranges[2 * r + 1]; if (ke > kEnd) kEnd = ke; }
    }
    const int nt  = kEnd / BN;
    const int nch = (nt + CHUNK_TILES - 1) / CHUNK_TILES;
    if (chunk >= nch) return;
    const int csz = (nt + nch - 1) / nch;       // balanced chunk size
    const int tS = chunk * csz;
    const int tE = min(nt, tS + csz);

    const int mwBase = (wid & 3) * 32;   // q rows this warp-pair owns (2 m-frags)
    const int nw     = wid >> 2;         // QK: key group; PV: d group
    const int pairBar = 1 + (wid & 3);   // named barrier per warp pair {w, w+4}

    // ---- prologue: Q + first tile, one cp.async group ----
#pragma unroll
    for (int j = 0; j < 8; ++j) {
        int idx = tid + j * 256;
        int row = idx >> 4, c = idx & 15;
        size_t gof = ((size_t)(q0 + row) * HQn + head) * DH + c * 8;
        cpa(sb + OFF_Q + row * 256 + swz(c, row) * 16, g_qh + gof);
    }
    load_tile(sb, tS * BN, 0, hk, tid);
    CP_COMMIT();

    float O[2][8][4];
    float lsum[2][2];
#pragma unroll
    for (int mf = 0; mf < 2; ++mf) {
        lsum[mf][0] = lsum[mf][1] = 0.f;
#pragma unroll
        for (int nf = 0; nf < 8; ++nf)
#pragma unroll
            for (int e = 0; e < 4; ++e) O[mf][nf][e] = 0.f;
    }

    const float kC = 0.127532019f;   // log2(e)/sqrt(128)

    for (int t = tS; t < tE; ++t) {
        const int s = (t - tS) & 1;

        CP_WAIT0();
        __syncthreads();                       // tile t ready; PV(t-1) done everywhere
        if (t + 1 < tE) { load_tile(sb, (t + 1) * BN, s ^ 1, hk, tid); CP_COMMIT(); }

        // ---------- QK: S(m32 x n32) = Q . K^T ----------
        float S[2][4][4];
#pragma unroll
        for (int mf = 0; mf < 2; ++mf)
#pragma unroll
            for (int nf = 0; nf < 4; ++nf)
#pragma unroll
                for (int e = 0; e < 4; ++e) S[mf][nf][e] = 0.f;

        const uint32_t Kb = sb + OFF_K(s);
        const uint32_t Qb = sb + OFF_Q;
#pragma unroll
        for (int ks = 0; ks < 8; ++ks) {
            uint32_t kb[8];
            {
                int rowK = nw * 32 + ((lane >> 4) << 3) + (lane & 7);
                int ch = 2 * ks + ((lane >> 3) & 1);
                ldsm4(kb,     Kb + rowK * 256 + swz(ch, rowK) * 16);
                int rowK2 = rowK + 16;
                ldsm4(kb + 4, Kb + rowK2 * 256 + swz(ch, rowK2) * 16);
            }
#pragma unroll
            for (int mf = 0; mf < 2; ++mf) {
                uint32_t a[4];
                int rowA = mwBase + mf * 16 + (lane & 15);
                int ch = 2 * ks + (lane >> 4);
                ldsm4(a, Qb + rowA * 256 + swz(ch, rowA) * 16);
                hmma(S[mf][0], a, kb + 0);
                hmma(S[mf][1], a, kb + 2);
                hmma(S[mf][2], a, kb + 4);
                hmma(S[mf][3], a, kb + 6);
            }
        }

        // ---------- softmax (no max-sub) + P to smem (pair-shared rows) ----------
        {
            char* PH = smem + OFF_P;
#pragma unroll
            for (int mf = 0; mf < 2; ++mf) {
                int rg = mwBase + mf * 16 + g;
                int rh = rg + 8;
#pragma unroll
                for (int nf = 0; nf < 4; ++nf) {
                    float p0 = ex2(S[mf][nf][0] * kC);
                    float p1 = ex2(S[mf][nf][1] * kC);
                    float p2 = ex2(S[mf][nf][2] * kC);
                    float p3 = ex2(S[mf][nf][3] * kC);
                    lsum[mf][0] += p0 + p1;
                    lsum[mf][1] += p2 + p3;
                    int c = nw * 4 + nf;
                    int b0 = rg * 128 + ((c ^ (rg & 7)) * 16) + 4 * tq4;
                    int b1 = rh * 128 + ((c ^ (rh & 7)) * 16) + 4 * tq4;
                    *(__half2*)(PH + b0) = __floats2half2_rn(p0, p1);
                    *(__half2*)(PH + b1) = __floats2half2_rn(p2, p3);
                }
            }
        }
        // warps w and w+4 share P rows (columns split) -> pair barrier
        asm volatile("bar.sync %0, 64;" :: "r"(pairBar) : "memory");

        // ---------- PV: O(m32 x d64) += P . V ----------
        const uint32_t Vb = sb + OFF_V(s);
        const uint32_t Pa = sb + OFF_P;
#pragma unroll
        for (int ks = 0; ks < 4; ++ks) {
            uint32_t vb[16];
#pragma unroll
            for (int nfp = 0; nfp < 4; ++nfp) {
                int rowV = ks * 16 + (lane & 15);
                int cd = nw * 8 + nfp * 2 + (lane >> 4);
                ldsm4t(vb + nfp * 4, Vb + rowV * 256 + swz(cd, rowV) * 16);
            }
#pragma unroll
            for (int mf = 0; mf < 2; ++mf) {
                uint32_t a[4];
                int rowA = mwBase + mf * 16 + (lane & 15);
                int ch = 2 * ks + (lane >> 4);
                ldsm4(a, Pa + rowA * 128 + ((ch ^ (rowA & 7)) * 16));
#pragma unroll
                for (int nf = 0; nf < 8; ++nf)
                    hmma(O[mf][nf], a, vb + nf * 2);
            }
        }
    }

    // ---- l reduction across quad lanes; lb reuses P space ----
    __syncthreads();                           // last PV reads of P done
    float* lb = (float*)(smem + OFF_LB);
#pragma unroll
    for (int mf = 0; mf < 2; ++mf)
#pragma unroll
        for (int h = 0; h < 2; ++h) {
            float v = lsum[mf][h];
            v += __shfl_xor_sync(0xffffffffu, v, 1);
            v += __shfl_xor_sync(0xffffffffu, v, 2);
            lsum[mf][h] = v;
        }
    if (tq4 == 0) {
#pragma unroll
        for (int mf = 0; mf < 2; ++mf) {
            int rg = mwBase + mf * 16 + g;
            lb[rg * 2 + nw]       = lsum[mf][0];
            lb[(rg + 8) * 2 + nw] = lsum[mf][1];
        }
    }
    __syncthreads();

    if (nch == 1) {
        // ---- direct epilogue: normalize + store ----
#pragma unroll
        for (int mf = 0; mf < 2; ++mf) {
            int rg = mwBase + mf * 16 + g;
            int rh = rg + 8;
            float ig = 1.0f / (lb[rg * 2] + lb[rg * 2 + 1]);
            float ih = 1.0f / (lb[rh * 2] + lb[rh * 2 + 1]);
            float* og = out + ((size_t)(q0 + rg) * HQn + head) * DH;
            float* oh = out + ((size_t)(q0 + rh) * HQn + head) * DH;
#pragma unroll
            for (int nf = 0; nf < 8; ++nf) {
                int d = nw * 64 + nf * 8 + 2 * tq4;
                *(float2*)(og + d) = make_float2(O[mf][nf][0] * ig, O[mf][nf][1] * ig);
                *(float2*)(oh + d) = make_float2(O[mf][nf][2] * ih, O[mf][nf][3] * ih);
            }
        }
        return;
    }

    // ---- split epilogue: unnormalized partial O + l to scratch ----
    const int hq16 = head * 16 + qt;
    const size_t base = (size_t)hq16 * MAXCH;
    {
        float* po = g_po + (base + chunk) * (BM * DH);
        float* pl = g_pl + (base + chunk) * BM;
#pragma unroll
        for (int mf = 0; mf < 2; ++mf) {
            int rg = mwBase + mf * 16 + g;
            int rh = rg + 8;
            if (tq4 == 0 && nw == 0) {
                pl[rg] = lb[rg * 2] + lb[rg * 2 + 1];
                pl[rh] = lb[rh * 2] + lb[rh * 2 + 1];
            }
            float* og = po + rg * DH;
            float* oh = po + rh * DH;
#pragma unroll
            for (int nf = 0; nf < 8; ++nf) {
                int d = nw * 64 + nf * 8 + 2 * tq4;
                *(float2*)(og + d) = make_float2(O[mf][nf][0], O[mf][nf][1]);
                *(float2*)(oh + d) = make_float2(O[mf][nf][2], O[mf][nf][3]);
            }
        }
    }

    // ---- election: last-arriving chunk reduces ----
    __threadfence();
    __syncthreads();
    int* flag = (int*)(smem + OFF_FLAG);
    if (tid == 0) *flag = atomicAdd(&g_cnt[hq16], 1);
    __syncthreads();
    if (*flag != nch - 1) return;

    // this CTA is the reducer
    if (tid == 0) g_cnt[hq16] = 0;             // reset for next graph replay
    __threadfence();
    float* linv = (float*)(smem + OFF_LB);
    if (tid < BM) {
        float l = 0.f;
        for (int c = 0; c < nch; ++c) l += g_pl[(base + c) * BM + tid];
        linv[tid] = 1.0f / l;
    }
    __syncthreads();

    const float4* po4 = (const float4*)(g_po + base * (BM * DH));
#pragma unroll
    for (int i = 0; i < 16; ++i) {
        int idx = tid + i * 256;               // 4096 float4 = 128x128
        int row = idx >> 5;
        float4 acc = po4[idx];
        for (int c = 1; c < nch; ++c) {
            float4 w = po4[(size_t)c * (BM * DH / 4) + idx];
            acc.x += w.x; acc.y += w.y; acc.z += w.z; acc.w += w.w;
        }
        float sc = linv[row];
        acc.x *= sc; acc.y *= sc; acc.z *= sc; acc.w *= sc;
        int d = (idx & 31) * 4;
        *(float4*)(out + ((size_t)(q0 + row) * HQn + head) * DH + d) = acc;
    }
}

extern "C" void kernel_launch(void* const* d_in, const int* in_sizes, int n_in,
                              void* d_out, int out_size) {
    const float* q  = (const float*)d_in[0];
    const float* k  = (const float*)d_in[1];
    const float* v  = (const float*)d_in[2];
    const float* cs = (const float*)d_in[3];
    const float* sn = (const float*)d_in[4];
    const int*   qr = (const int*)d_in[5];
    const int*   kr = (const int*)d_in[6];
    const int nR = in_sizes[5] / 2;
    float* out = (float*)d_out;

    cudaFuncSetAttribute(attn_kernel,
                         cudaFuncAttributeMaxDynamicSharedMemorySize, SMEM_TOTAL);

    prep_kernel<<<QBLK + KBLK + VBLK, 256>>>(q, k, v, cs, sn);
    attn_kernel<<<(TT / BM) * HQn * MAXCH, NTH, SMEM_TOTAL>>>(qr, kr, nR, out);
}